// round 8
// baseline (speedup 1.0000x reference)
#include <cuda_runtime.h>

#define N_NODES 100000
#define E_MSG   3200000
#define E_SC    1000000
#define IN_DIM  12
#define HID     64
#define EMB     32
#define EDGE_F  10
#define EDGE_REPR 74
#define D2PAD   76   // dec_W2 row padded to multiple of 4

// ---------------- scratch (static device globals; no allocation) -------------
__device__ float g_agg1 [N_NODES * IN_DIM];
__device__ float g_cnt  [N_NODES];
__device__ float g_h    [N_NODES * HID];
__device__ float g_p    [N_NODES * EMB];   // h @ Wn2 (projected, 32-dim)
__device__ float g_agg2p[N_NODES * EMB];   // scatter of g_p
__device__ float g_emb  [N_NODES * EMB];
__device__ float g_P1   [N_NODES * HID];   // emb @ W1a + b1
__device__ float g_P2   [N_NODES * HID];   // emb @ W1b

// ---------------- int32/int64 index handling ---------------------------------
__device__ __forceinline__ bool idx_is64(const void* p) {
    const int* q = (const int*)p;
    return (q[1] | q[3] | q[5]) == 0;
}
__device__ __forceinline__ long long ld_idx(const void* p, long long i, bool is64) {
    if (is64) return ((const long long*)p)[i];
    return (long long)((const int*)p)[i];
}

__device__ __forceinline__ float warp_sum(float v) {
#pragma unroll
    for (int o = 16; o > 0; o >>= 1) v += __shfl_xor_sync(0xffffffffu, v, o);
    return v;
}

// ---------------- packed f32x2 helpers (sm_100+) ------------------------------
__device__ __forceinline__ unsigned long long pk2(float a, float b) {
    unsigned long long r;
    asm("mov.b64 %0, {%1,%2};" : "=l"(r) : "f"(a), "f"(b));
    return r;
}
__device__ __forceinline__ void upk2(unsigned long long p, float& a, float& b) {
    asm("mov.b64 {%0,%1}, %2;" : "=f"(a), "=f"(b) : "l"(p));
}
__device__ __forceinline__ void fma2(unsigned long long& d,
                                     unsigned long long a, unsigned long long b) {
    asm("fma.rn.f32x2 %0, %1, %2, %0;" : "+l"(d) : "l"(a), "l"(b));
}
__device__ __forceinline__ unsigned long long add2(unsigned long long a,
                                                   unsigned long long b) {
    unsigned long long r;
    asm("add.rn.f32x2 %0, %1, %2;" : "=l"(r) : "l"(a), "l"(b));
    return r;
}

// ---------------- vector float atomic (sm_90+) --------------------------------
__device__ __forceinline__ void red_add_v4(float* addr, float4 v) {
    asm volatile("red.global.add.v4.f32 [%0], {%1,%2,%3,%4};"
                 :: "l"(addr), "f"(v.x), "f"(v.y), "f"(v.z), "f"(v.w) : "memory");
}

// ---------------- zero scratch ------------------------------------------------
__global__ __launch_bounds__(256) void zero_kernel() {
    int i = blockIdx.x * 256 + threadIdx.x;
    const int A1 = N_NODES * IN_DIM;            // 1.2M
    const int A2 = A1 + N_NODES;                // +0.1M
    const int A3 = A2 + N_NODES * EMB;          // +3.2M
    if (i < A1)      g_agg1[i] = 0.f;
    else if (i < A2) g_cnt[i - A1] = 0.f;
    else if (i < A3) g_agg2p[i - A2] = 0.f;
}

// ---------------- scatter layer-1 features + degree counts -------------------
__global__ __launch_bounds__(256) void scatter1_kernel(const void* __restrict__ ei,
                                                       const float* __restrict__ nf) {
    int e = blockIdx.x * 256 + threadIdx.x;
    if (e >= E_MSG) return;
    bool is64 = idx_is64(ei);
    long long s = ld_idx(ei, e, is64);
    long long d = ld_idx(ei, (long long)E_MSG + e, is64);
    const float4* x = (const float4*)(nf + s * IN_DIM);   // 48B rows, 16B aligned
    float* a = g_agg1 + d * IN_DIM;
#pragma unroll
    for (int j = 0; j < 3; j++) red_add_v4(a + 4 * j, x[j]);
    atomicAdd(g_cnt + d, 1.f);
}

// ---------------- SAGE layer 1: 12 -> 64 + LN + relu, fused proj h@Wn2 -------
__global__ __launch_bounds__(256) void sage1_kernel(const float* __restrict__ nf,
                                                    const float* __restrict__ Ws,
                                                    const float* __restrict__ Wn,
                                                    const float* __restrict__ b,
                                                    const float* __restrict__ g,
                                                    const float* __restrict__ be,
                                                    const float* __restrict__ Wn2) {
    __shared__ float sWs[IN_DIM * HID], sWn[IN_DIM * HID], sW2[HID * EMB];
    __shared__ float sb[HID], sg[HID], sbe[HID];
    for (int i = threadIdx.x; i < IN_DIM * HID; i += 256) { sWs[i] = Ws[i]; sWn[i] = Wn[i]; }
    for (int i = threadIdx.x; i < HID * EMB; i += 256) sW2[i] = Wn2[i];
    if (threadIdx.x < HID) {
        sb[threadIdx.x] = b[threadIdx.x];
        sg[threadIdx.x] = g[threadIdx.x];
        sbe[threadIdx.x] = be[threadIdx.x];
    }
    __syncthreads();
    int n = blockIdx.x * 8 + (threadIdx.x >> 5);
    int lane = threadIdx.x & 31;
    float inv = 1.f / fmaxf(g_cnt[n], 1.f);
    float h0 = sb[lane], h1 = sb[lane + 32];
#pragma unroll
    for (int k = 0; k < IN_DIM; k++) {
        float xk = nf[n * IN_DIM + k];
        float ak = g_agg1[n * IN_DIM + k] * inv;
        h0 += xk * sWs[k * HID + lane]      + ak * sWn[k * HID + lane];
        h1 += xk * sWs[k * HID + lane + 32] + ak * sWn[k * HID + lane + 32];
    }
    float s1 = warp_sum(h0 + h1);
    float s2 = warp_sum(h0 * h0 + h1 * h1);
    float mu  = s1 * (1.f / 64.f);
    float var = s2 * (1.f / 64.f) - mu * mu;
    float r = rsqrtf(var + 1e-5f);
    float o0 = fmaxf((h0 - mu) * r * sg[lane]      + sbe[lane],      0.f);
    float o1 = fmaxf((h1 - mu) * r * sg[lane + 32] + sbe[lane + 32], 0.f);
    g_h[n * HID + lane]      = o0;
    g_h[n * HID + lane + 32] = o1;
    // fused projection: p = h @ Wn2 (h is lane-distributed in o0/o1)
    float acc = 0.f;
#pragma unroll
    for (int k = 0; k < 32; k++)
        acc += __shfl_sync(0xffffffffu, o0, k) * sW2[k * EMB + lane];
#pragma unroll
    for (int k = 0; k < 32; k++)
        acc += __shfl_sync(0xffffffffu, o1, k) * sW2[(k + 32) * EMB + lane];
    g_p[n * EMB + lane] = acc;
}

// ---------------- scatter layer-2 (projected): p[src] -> agg2p[dst] ----------
__global__ __launch_bounds__(256) void scatter2_kernel(const void* __restrict__ ei) {
    int e = blockIdx.x * 256 + threadIdx.x;
    if (e >= E_MSG) return;
    bool is64 = idx_is64(ei);
    long long s = ld_idx(ei, e, is64);
    long long d = ld_idx(ei, (long long)E_MSG + e, is64);
    const float4* ps = (const float4*)(g_p + s * EMB);    // 128B rows
    float* pd = g_agg2p + d * EMB;
#pragma unroll
    for (int j = 0; j < 8; j++) red_add_v4(pd + 4 * j, ps[j]);
}

// ---------------- SAGE layer 2: 64 -> 32 + LN + relu -------------------------
__global__ __launch_bounds__(256) void sage2_kernel(const float* __restrict__ Ws,
                                                    const float* __restrict__ b,
                                                    const float* __restrict__ g,
                                                    const float* __restrict__ be) {
    __shared__ float sWs[HID * EMB];
    __shared__ float sb[EMB], sg[EMB], sbe[EMB];
    for (int i = threadIdx.x; i < HID * EMB; i += 256) sWs[i] = Ws[i];
    if (threadIdx.x < EMB) {
        sb[threadIdx.x] = b[threadIdx.x];
        sg[threadIdx.x] = g[threadIdx.x];
        sbe[threadIdx.x] = be[threadIdx.x];
    }
    __syncthreads();
    int n = blockIdx.x * 8 + (threadIdx.x >> 5);
    int lane = threadIdx.x & 31;
    float inv = 1.f / fmaxf(g_cnt[n], 1.f);
    float hl = g_h[n * HID + lane];
    float hh = g_h[n * HID + 32 + lane];
    float acc = sb[lane] + g_agg2p[n * EMB + lane] * inv;
#pragma unroll
    for (int k = 0; k < 32; k++)
        acc += __shfl_sync(0xffffffffu, hl, k) * sWs[k * EMB + lane];
#pragma unroll
    for (int k = 0; k < 32; k++)
        acc += __shfl_sync(0xffffffffu, hh, k) * sWs[(k + 32) * EMB + lane];
    float s1 = warp_sum(acc);
    float s2 = warp_sum(acc * acc);
    float mu  = s1 * (1.f / 32.f);
    float var = s2 * (1.f / 32.f) - mu * mu;
    float r = rsqrtf(var + 1e-5f);
    g_emb[n * EMB + lane] = fmaxf((acc - mu) * r * sg[lane] + sbe[lane], 0.f);
}

// ---------------- precompute enc1 node projections ---------------------------
// P1[n] = emb[n] @ W1a + b1   (W1a = eW1 rows 0..31)
// P2[n] = emb[n] @ W1b        (W1b = eW1 rows 32..63)
__global__ __launch_bounds__(256) void proj_enc_kernel(const float* __restrict__ eW1,
                                                       const float* __restrict__ eb1) {
    __shared__ float sA[EMB * HID], sB[EMB * HID], sb1[HID];
    for (int i = threadIdx.x; i < EMB * HID; i += 256) {
        sA[i] = eW1[i];
        sB[i] = eW1[EMB * HID + i];
    }
    if (threadIdx.x < HID) sb1[threadIdx.x] = eb1[threadIdx.x];
    __syncthreads();
    int n = blockIdx.x * 8 + (threadIdx.x >> 5);
    int lane = threadIdx.x & 31;
    float ev = g_emb[n * EMB + lane];
    float p10 = sb1[lane], p11 = sb1[lane + 32];
    float p20 = 0.f, p21 = 0.f;
#pragma unroll
    for (int k = 0; k < EMB; k++) {
        float e = __shfl_sync(0xffffffffu, ev, k);
        p10 += e * sA[k * HID + lane];
        p11 += e * sA[k * HID + lane + 32];
        p20 += e * sB[k * HID + lane];
        p21 += e * sB[k * HID + lane + 32];
    }
    g_P1[n * HID + lane]      = p10;
    g_P1[n * HID + lane + 32] = p11;
    g_P2[n * HID + lane]      = p20;
    g_P2[n * HID + lane + 32] = p21;
}

// ---------------- fused edge_rep + edge MLP (packed f32x2) -------------------
// Shared layout (floats): W1c(10*64) W2(64*32) D1(32*64) D2(64*76) b2(32) b3(64) b4(76)
#define SM_W1C 0
#define SM_W2 (SM_W1C + EDGE_F * HID)
#define SM_D1 (SM_W2 + HID * EMB)
#define SM_D2 (SM_D1 + EMB * HID)
#define SM_B2 (SM_D2 + HID * D2PAD)
#define SM_B3 (SM_B2 + EMB)
#define SM_B4 (SM_B3 + HID)
#define SM_TOTAL (SM_B4 + D2PAD)   // 9772 floats = 39088 B

#define MLP_THREADS 128

__global__ __launch_bounds__(MLP_THREADS, 3) void edge_mlp_kernel(
    const void* __restrict__ srcn, const void* __restrict__ dstn,
    const float* __restrict__ ea,
    const float* __restrict__ eW1,
    const float* __restrict__ eW2, const float* __restrict__ eb2,
    const float* __restrict__ dW1, const float* __restrict__ db1,
    const float* __restrict__ dW2, const float* __restrict__ db2,
    float* __restrict__ out_recon, float* __restrict__ out_er) {
    extern __shared__ float sm[];
    for (int i = threadIdx.x; i < EDGE_F * HID; i += MLP_THREADS)
        sm[SM_W1C + i] = eW1[2 * EMB * HID + i];          // rows 64..73
    for (int i = threadIdx.x; i < HID * EMB; i += MLP_THREADS) sm[SM_W2 + i] = eW2[i];
    for (int i = threadIdx.x; i < EMB * HID; i += MLP_THREADS) sm[SM_D1 + i] = dW1[i];
    for (int i = threadIdx.x; i < HID * D2PAD; i += MLP_THREADS) {
        int k = i / D2PAD, j = i - k * D2PAD;
        sm[SM_D2 + i] = (j < EDGE_REPR) ? dW2[k * EDGE_REPR + j] : 0.f;
    }
    for (int i = threadIdx.x; i < HID; i += MLP_THREADS)   sm[SM_B3 + i] = db1[i];
    for (int i = threadIdx.x; i < EMB; i += MLP_THREADS)   sm[SM_B2 + i] = eb2[i];
    for (int i = threadIdx.x; i < D2PAD; i += MLP_THREADS) sm[SM_B4 + i] = (i < EDGE_REPR) ? db2[i] : 0.f;
    __syncthreads();

    int e = blockIdx.x * MLP_THREADS + threadIdx.x;
    if (e >= E_SC) return;
    bool is64s = idx_is64(srcn);
    bool is64d = idx_is64(dstn);
    long long s = ld_idx(srcn, e, is64s);
    long long d = ld_idx(dstn, e, is64d);

    // -------- gather + write edge representation (out_er) --------
    float eaf[EDGE_F];
#pragma unroll
    for (int i = 0; i < EDGE_F; i++) eaf[i] = ea[(long long)e * EDGE_F + i];
    {
        const float4* es = (const float4*)(g_emb + s * EMB);
        const float4* ed = (const float4*)(g_emb + d * EMB);
        unsigned long long* o = (unsigned long long*)(out_er + (long long)e * EDGE_REPR);
#pragma unroll
        for (int j = 0; j < 8; j++) {
            float4 v = es[j];
            o[2 * j]     = pk2(v.x, v.y);
            o[2 * j + 1] = pk2(v.z, v.w);
        }
#pragma unroll
        for (int j = 0; j < 8; j++) {
            float4 v = ed[j];
            o[16 + 2 * j]     = pk2(v.x, v.y);
            o[16 + 2 * j + 1] = pk2(v.z, v.w);
        }
#pragma unroll
        for (int j = 0; j < EDGE_F / 2; j++)
            o[32 + j] = pk2(eaf[2 * j], eaf[2 * j + 1]);
    }

    // -------- enc1: a1 = P1[s] + P2[d] + ea @ W1c, relu --------
    unsigned long long a1[HID / 2];
    {
        const ulonglong2* p1 = (const ulonglong2*)(g_P1 + s * HID);
        const ulonglong2* p2 = (const ulonglong2*)(g_P2 + d * HID);
#pragma unroll
        for (int j = 0; j < HID / 4; j++) {
            ulonglong2 x = p1[j];
            ulonglong2 y = p2[j];
            a1[2 * j]     = add2(x.x, y.x);
            a1[2 * j + 1] = add2(x.y, y.y);
        }
#pragma unroll
        for (int k = 0; k < EDGE_F; k++) {
            unsigned long long ek = pk2(eaf[k], eaf[k]);
            const ulonglong2* w = (const ulonglong2*)(sm + SM_W1C + k * HID);
#pragma unroll
            for (int j = 0; j < HID / 4; j++) {
                ulonglong2 t = w[j];
                fma2(a1[2 * j], ek, t.x);
                fma2(a1[2 * j + 1], ek, t.y);
            }
        }
    }
    float r1[HID];
#pragma unroll
    for (int j = 0; j < HID / 2; j++) upk2(a1[j], r1[2 * j], r1[2 * j + 1]);
#pragma unroll
    for (int j = 0; j < HID; j++) r1[j] = fmaxf(r1[j], 0.f);

    // -------- enc2: 64 -> 32, relu --------
    unsigned long long a2[EMB / 2];
    {
        const unsigned long long* bp = (const unsigned long long*)(sm + SM_B2);
#pragma unroll
        for (int j = 0; j < EMB / 2; j++) a2[j] = bp[j];
#pragma unroll
        for (int k = 0; k < HID; k++) {
            unsigned long long rk = pk2(r1[k], r1[k]);
            const ulonglong2* w = (const ulonglong2*)(sm + SM_W2 + k * EMB);
#pragma unroll
            for (int j = 0; j < EMB / 4; j++) {
                ulonglong2 t = w[j];
                fma2(a2[2 * j], rk, t.x);
                fma2(a2[2 * j + 1], rk, t.y);
            }
        }
    }
    float lat[EMB];
#pragma unroll
    for (int j = 0; j < EMB / 2; j++) upk2(a2[j], lat[2 * j], lat[2 * j + 1]);
#pragma unroll
    for (int j = 0; j < EMB; j++) lat[j] = fmaxf(lat[j], 0.f);

    // -------- dec1: 32 -> 64, relu --------
    unsigned long long a3[HID / 2];
    {
        const unsigned long long* bp = (const unsigned long long*)(sm + SM_B3);
#pragma unroll
        for (int j = 0; j < HID / 2; j++) a3[j] = bp[j];
#pragma unroll
        for (int k = 0; k < EMB; k++) {
            unsigned long long lk = pk2(lat[k], lat[k]);
            const ulonglong2* w = (const ulonglong2*)(sm + SM_D1 + k * HID);
#pragma unroll
            for (int j = 0; j < HID / 4; j++) {
                ulonglong2 t = w[j];
                fma2(a3[2 * j], lk, t.x);
                fma2(a3[2 * j + 1], lk, t.y);
            }
        }
    }
    float h2[HID];
#pragma unroll
    for (int j = 0; j < HID / 2; j++) upk2(a3[j], h2[2 * j], h2[2 * j + 1]);
#pragma unroll
    for (int j = 0; j < HID; j++) h2[j] = fmaxf(h2[j], 0.f);

    // -------- dec2: 64 -> 74 (padded 76), no relu --------
    unsigned long long a4[D2PAD / 2];
    {
        const unsigned long long* bp = (const unsigned long long*)(sm + SM_B4);
#pragma unroll
        for (int j = 0; j < D2PAD / 2; j++) a4[j] = bp[j];
#pragma unroll
        for (int k = 0; k < HID; k++) {
            unsigned long long hk = pk2(h2[k], h2[k]);
            const ulonglong2* w = (const ulonglong2*)(sm + SM_D2 + k * D2PAD);
#pragma unroll
            for (int j = 0; j < D2PAD / 4; j++) {
                ulonglong2 t = w[j];
                fma2(a4[2 * j], hk, t.x);
                fma2(a4[2 * j + 1], hk, t.y);
            }
        }
    }
    {
        unsigned long long* o = (unsigned long long*)(out_recon + (long long)e * EDGE_REPR);
#pragma unroll
        for (int j = 0; j < EDGE_REPR / 2; j++) o[j] = a4[j];  // pairs 0..36 = cols 0..73
    }
}

// ---------------- launcher ----------------------------------------------------
extern "C" void kernel_launch(void* const* d_in, const int* in_sizes, int n_in,
                              void* d_out, int out_size) {
    const float* nf   = (const float*)d_in[0];
    const void*  ei   = d_in[1];
    const float* ea   = (const float*)d_in[2];
    const void*  srcn = d_in[3];
    const void*  dstn = d_in[4];
    const float* Ws1 = (const float*)d_in[5];
    const float* Wn1 = (const float*)d_in[6];
    const float* b1  = (const float*)d_in[7];
    const float* g1  = (const float*)d_in[8];
    const float* be1 = (const float*)d_in[9];
    const float* Ws2 = (const float*)d_in[10];
    const float* Wn2 = (const float*)d_in[11];
    const float* b2  = (const float*)d_in[12];
    const float* g2  = (const float*)d_in[13];
    const float* be2 = (const float*)d_in[14];
    const float* eW1 = (const float*)d_in[15];
    const float* eb1 = (const float*)d_in[16];
    const float* eW2 = (const float*)d_in[17];
    const float* eb2 = (const float*)d_in[18];
    const float* dW1 = (const float*)d_in[19];
    const float* db1 = (const float*)d_in[20];
    const float* dW2 = (const float*)d_in[21];
    const float* db2 = (const float*)d_in[22];

    float* out_recon = (float*)d_out;                                   // [1M, 74]
    float* out_er    = (float*)d_out + (long long)E_SC * EDGE_REPR;     // [1M, 74]

    const int smem_mlp = SM_TOTAL * sizeof(float);  // 39088 B
    cudaFuncSetAttribute(edge_mlp_kernel, cudaFuncAttributeMaxDynamicSharedMemorySize, smem_mlp);

    const int zero_total = N_NODES * IN_DIM + N_NODES + N_NODES * EMB;
    zero_kernel<<<(zero_total + 255) / 256, 256>>>();
    scatter1_kernel<<<(E_MSG + 255) / 256, 256>>>(ei, nf);
    sage1_kernel<<<N_NODES / 8, 256>>>(nf, Ws1, Wn1, b1, g1, be1, Wn2);
    scatter2_kernel<<<(E_MSG + 255) / 256, 256>>>(ei);
    sage2_kernel<<<N_NODES / 8, 256>>>(Ws2, b2, g2, be2);
    proj_enc_kernel<<<N_NODES / 8, 256>>>(eW1, eb1);
    edge_mlp_kernel<<<(E_SC + MLP_THREADS - 1) / MLP_THREADS, MLP_THREADS, smem_mlp>>>(
        srcn, dstn, ea, eW1, eW2, eb2, dW1, db1, dW2, db2, out_recon, out_er);
}

// round 9
// speedup vs baseline: 1.4279x; 1.4279x over previous
#include <cuda_runtime.h>

#define N_NODES 100000
#define E_MSG   3200000
#define E_SC    1000000
#define IN_DIM  12
#define HID     64
#define EMB     32
#define EDGE_F  10
#define EDGE_REPR 74
#define D2PAD   76   // dec_W2 row padded to multiple of 4

// ---------------- scratch (static device globals; no allocation) -------------
__device__ int   g_deg [N_NODES];        // zero-init at load; sage2 re-zeroes
__device__ int   g_off [N_NODES];
__device__ int   g_pos [N_NODES];
__device__ int   g_srclist[E_MSG];
__device__ float g_h   [N_NODES * HID];
__device__ float g_p   [N_NODES * EMB];  // h @ Wn2 (projected, 32-dim)
__device__ float g_emb [N_NODES * EMB];

// ---------------- int32/int64 index handling ---------------------------------
__device__ __forceinline__ bool idx_is64(const void* p) {
    const int* q = (const int*)p;
    return (q[1] | q[3] | q[5]) == 0;
}
__device__ __forceinline__ long long ld_idx(const void* p, long long i, bool is64) {
    if (is64) return ((const long long*)p)[i];
    return (long long)((const int*)p)[i];
}

__device__ __forceinline__ float warp_sum(float v) {
#pragma unroll
    for (int o = 16; o > 0; o >>= 1) v += __shfl_xor_sync(0xffffffffu, v, o);
    return v;
}

// ---------------- packed f32x2 helpers (sm_100+) ------------------------------
__device__ __forceinline__ unsigned long long pk2(float a, float b) {
    unsigned long long r;
    asm("mov.b64 %0, {%1,%2};" : "=l"(r) : "f"(a), "f"(b));
    return r;
}
__device__ __forceinline__ void upk2(unsigned long long p, float& a, float& b) {
    asm("mov.b64 {%0,%1}, %2;" : "=f"(a), "=f"(b) : "l"(p));
}
__device__ __forceinline__ void fma2(unsigned long long& d,
                                     unsigned long long a, unsigned long long b) {
    asm("fma.rn.f32x2 %0, %1, %2, %0;" : "+l"(d) : "l"(a), "l"(b));
}

// ---------------- CSR build ---------------------------------------------------
__global__ __launch_bounds__(256) void hist_kernel(const void* __restrict__ ei) {
    int e = blockIdx.x * 256 + threadIdx.x;
    if (e >= E_MSG) return;
    bool is64 = idx_is64(ei);
    int d = (int)ld_idx(ei, (long long)E_MSG + e, is64);
    atomicAdd(&g_deg[d], 1);
}

// single-block exclusive scan of g_deg -> g_off (and g_pos copy)
__global__ __launch_bounds__(1024) void scan_kernel() {
    __shared__ int part[1024];
    int t = threadIdx.x;
    const int CH = (N_NODES + 1023) / 1024;   // 98
    int base = t * CH;
    int s = 0;
    for (int i = 0; i < CH; i++) {
        int n = base + i;
        if (n < N_NODES) s += g_deg[n];
    }
    part[t] = s;
    __syncthreads();
    for (int o = 1; o < 1024; o <<= 1) {
        int v = (t >= o) ? part[t - o] : 0;
        __syncthreads();
        part[t] += v;
        __syncthreads();
    }
    int prefix = (t == 0) ? 0 : part[t - 1];
    for (int i = 0; i < CH; i++) {
        int n = base + i;
        if (n < N_NODES) {
            g_off[n] = prefix;
            g_pos[n] = prefix;
            prefix += g_deg[n];
        }
    }
}

__global__ __launch_bounds__(256) void fill_kernel(const void* __restrict__ ei) {
    int e = blockIdx.x * 256 + threadIdx.x;
    if (e >= E_MSG) return;
    bool is64 = idx_is64(ei);
    int s = (int)ld_idx(ei, e, is64);
    int d = (int)ld_idx(ei, (long long)E_MSG + e, is64);
    int p = atomicAdd(&g_pos[d], 1);
    g_srclist[p] = s;
}

// ---------------- SAGE layer 1 (CSR gather agg): 12 -> 64 + LN + relu + proj --
__global__ __launch_bounds__(256) void sage1_kernel(const float* __restrict__ nf,
                                                    const float* __restrict__ Ws,
                                                    const float* __restrict__ Wn,
                                                    const float* __restrict__ b,
                                                    const float* __restrict__ g,
                                                    const float* __restrict__ be,
                                                    const float* __restrict__ Wn2) {
    __shared__ float sWs[IN_DIM * HID], sWn[IN_DIM * HID], sW2[HID * EMB];
    __shared__ float sb[HID], sg[HID], sbe[HID];
    for (int i = threadIdx.x; i < IN_DIM * HID; i += 256) { sWs[i] = Ws[i]; sWn[i] = Wn[i]; }
    for (int i = threadIdx.x; i < HID * EMB; i += 256) sW2[i] = Wn2[i];
    if (threadIdx.x < HID) {
        sb[threadIdx.x] = b[threadIdx.x];
        sg[threadIdx.x] = g[threadIdx.x];
        sbe[threadIdx.x] = be[threadIdx.x];
    }
    __syncthreads();
    int n = blockIdx.x * 8 + (threadIdx.x >> 5);
    int lane = threadIdx.x & 31;
    int start = g_off[n];
    int deg   = g_deg[n];

    // lane-parallel gather of neighbor features
    float ax[IN_DIM];
#pragma unroll
    for (int k = 0; k < IN_DIM; k++) ax[k] = 0.f;
    for (int e = lane; e < deg; e += 32) {
        int src = g_srclist[start + e];
        const float4* x4 = (const float4*)(nf + src * IN_DIM);
        float4 v0 = x4[0], v1 = x4[1], v2 = x4[2];
        ax[0] += v0.x; ax[1] += v0.y; ax[2]  += v0.z; ax[3]  += v0.w;
        ax[4] += v1.x; ax[5] += v1.y; ax[6]  += v1.z; ax[7]  += v1.w;
        ax[8] += v2.x; ax[9] += v2.y; ax[10] += v2.z; ax[11] += v2.w;
    }
#pragma unroll
    for (int k = 0; k < IN_DIM; k++) {
#pragma unroll
        for (int o = 16; o > 0; o >>= 1) ax[k] += __shfl_xor_sync(0xffffffffu, ax[k], o);
    }
    float inv = 1.f / fmaxf((float)deg, 1.f);

    float h0 = sb[lane], h1 = sb[lane + 32];
#pragma unroll
    for (int k = 0; k < IN_DIM; k++) {
        float xk = nf[n * IN_DIM + k];
        float ak = ax[k] * inv;
        h0 += xk * sWs[k * HID + lane]      + ak * sWn[k * HID + lane];
        h1 += xk * sWs[k * HID + lane + 32] + ak * sWn[k * HID + lane + 32];
    }
    float s1 = warp_sum(h0 + h1);
    float s2 = warp_sum(h0 * h0 + h1 * h1);
    float mu  = s1 * (1.f / 64.f);
    float var = s2 * (1.f / 64.f) - mu * mu;
    float r = rsqrtf(var + 1e-5f);
    float o0 = fmaxf((h0 - mu) * r * sg[lane]      + sbe[lane],      0.f);
    float o1 = fmaxf((h1 - mu) * r * sg[lane + 32] + sbe[lane + 32], 0.f);
    g_h[n * HID + lane]      = o0;
    g_h[n * HID + lane + 32] = o1;
    // fused projection: p = h @ Wn2 (h is lane-distributed in o0/o1)
    float acc = 0.f;
#pragma unroll
    for (int k = 0; k < 32; k++)
        acc += __shfl_sync(0xffffffffu, o0, k) * sW2[k * EMB + lane];
#pragma unroll
    for (int k = 0; k < 32; k++)
        acc += __shfl_sync(0xffffffffu, o1, k) * sW2[(k + 32) * EMB + lane];
    g_p[n * EMB + lane] = acc;
}

// ---------------- SAGE layer 2 (CSR gather agg): 64 -> 32 + LN + relu --------
__global__ __launch_bounds__(256) void sage2_kernel(const float* __restrict__ Ws,
                                                    const float* __restrict__ b,
                                                    const float* __restrict__ g,
                                                    const float* __restrict__ be) {
    __shared__ float sWs[HID * EMB];
    __shared__ float sb[EMB], sg[EMB], sbe[EMB];
    for (int i = threadIdx.x; i < HID * EMB; i += 256) sWs[i] = Ws[i];
    if (threadIdx.x < EMB) {
        sb[threadIdx.x] = b[threadIdx.x];
        sg[threadIdx.x] = g[threadIdx.x];
        sbe[threadIdx.x] = be[threadIdx.x];
    }
    __syncthreads();
    int n = blockIdx.x * 8 + (threadIdx.x >> 5);
    int lane = threadIdx.x & 31;
    int start = g_off[n];
    int deg   = g_deg[n];

    // feature-parallel gather: each iteration reads a coalesced 128B row of g_p
    float accp = 0.f;
#pragma unroll 4
    for (int j = 0; j < deg; j++) {
        int src = g_srclist[start + j];
        accp += g_p[src * EMB + lane];
    }
    float inv = 1.f / fmaxf((float)deg, 1.f);

    float hl = g_h[n * HID + lane];
    float hh = g_h[n * HID + 32 + lane];
    float acc = sb[lane] + accp * inv;
#pragma unroll
    for (int k = 0; k < 32; k++)
        acc += __shfl_sync(0xffffffffu, hl, k) * sWs[k * EMB + lane];
#pragma unroll
    for (int k = 0; k < 32; k++)
        acc += __shfl_sync(0xffffffffu, hh, k) * sWs[(k + 32) * EMB + lane];
    float s1 = warp_sum(acc);
    float s2 = warp_sum(acc * acc);
    float mu  = s1 * (1.f / 32.f);
    float var = s2 * (1.f / 32.f) - mu * mu;
    float r = rsqrtf(var + 1e-5f);
    g_emb[n * EMB + lane] = fmaxf((acc - mu) * r * sg[lane] + sbe[lane], 0.f);

    // reset degree counter for the next call (graph replay invariant)
    if (lane == 0) g_deg[n] = 0;
}

// ---------------- fused edge_rep + edge MLP (packed f32x2) -------------------
// Shared layout (floats): W1(74*64) W2(64*32) D1(32*64) D2(64*76) b1(64) b2(32) b3(64) b4(76)
#define SM_W1 0
#define SM_W2 (SM_W1 + EDGE_REPR * HID)
#define SM_D1 (SM_W2 + HID * EMB)
#define SM_D2 (SM_D1 + EMB * HID)
#define SM_B1 (SM_D2 + HID * D2PAD)
#define SM_B2 (SM_B1 + HID)
#define SM_B3 (SM_B2 + EMB)
#define SM_B4 (SM_B3 + HID)
#define SM_TOTAL (SM_B4 + D2PAD)   // 13932 floats = 55728 B

#define MLP_THREADS 128

__global__ __launch_bounds__(MLP_THREADS, 3) void edge_mlp_kernel(
    const void* __restrict__ srcn, const void* __restrict__ dstn,
    const float* __restrict__ ea,
    const float* __restrict__ eW1, const float* __restrict__ eb1,
    const float* __restrict__ eW2, const float* __restrict__ eb2,
    const float* __restrict__ dW1, const float* __restrict__ db1,
    const float* __restrict__ dW2, const float* __restrict__ db2,
    float* __restrict__ out_recon, float* __restrict__ out_er) {
    extern __shared__ float sm[];
    for (int i = threadIdx.x; i < EDGE_REPR * HID; i += MLP_THREADS) sm[SM_W1 + i] = eW1[i];
    for (int i = threadIdx.x; i < HID * EMB; i += MLP_THREADS)       sm[SM_W2 + i] = eW2[i];
    for (int i = threadIdx.x; i < EMB * HID; i += MLP_THREADS)       sm[SM_D1 + i] = dW1[i];
    for (int i = threadIdx.x; i < HID * D2PAD; i += MLP_THREADS) {
        int k = i / D2PAD, j = i - k * D2PAD;
        sm[SM_D2 + i] = (j < EDGE_REPR) ? dW2[k * EDGE_REPR + j] : 0.f;
    }
    for (int i = threadIdx.x; i < HID; i += MLP_THREADS) { sm[SM_B1 + i] = eb1[i]; sm[SM_B3 + i] = db1[i]; }
    for (int i = threadIdx.x; i < EMB; i += MLP_THREADS)   sm[SM_B2 + i] = eb2[i];
    for (int i = threadIdx.x; i < D2PAD; i += MLP_THREADS) sm[SM_B4 + i] = (i < EDGE_REPR) ? db2[i] : 0.f;
    __syncthreads();

    int e = blockIdx.x * MLP_THREADS + threadIdx.x;
    if (e >= E_SC) return;
    bool is64s = idx_is64(srcn);
    bool is64d = idx_is64(dstn);
    long long s = ld_idx(srcn, e, is64s);
    long long d = ld_idx(dstn, e, is64d);

    // -------- gather edge representation --------
    float er[EDGE_REPR];
    {
        const float4* es = (const float4*)(g_emb + s * EMB);
        const float4* ed = (const float4*)(g_emb + d * EMB);
#pragma unroll
        for (int j = 0; j < 8; j++) {
            float4 v = es[j];
            er[4 * j] = v.x; er[4 * j + 1] = v.y; er[4 * j + 2] = v.z; er[4 * j + 3] = v.w;
        }
#pragma unroll
        for (int j = 0; j < 8; j++) {
            float4 v = ed[j];
            er[EMB + 4 * j] = v.x; er[EMB + 4 * j + 1] = v.y;
            er[EMB + 4 * j + 2] = v.z; er[EMB + 4 * j + 3] = v.w;
        }
#pragma unroll
        for (int i = 0; i < EDGE_F; i++) er[2 * EMB + i] = ea[(long long)e * EDGE_F + i];
    }
    // write edge_rep output (8B aligned: e*74*4 % 8 == 0)
    {
        unsigned long long* o = (unsigned long long*)(out_er + (long long)e * EDGE_REPR);
#pragma unroll
        for (int j = 0; j < EDGE_REPR / 2; j++) o[j] = pk2(er[2 * j], er[2 * j + 1]);
    }

    // -------- enc1: 74 -> 64, relu (packed pairs over output dim) --------
    unsigned long long a1[HID / 2];
    {
        const unsigned long long* bp = (const unsigned long long*)(sm + SM_B1);
#pragma unroll
        for (int j = 0; j < HID / 2; j++) a1[j] = bp[j];
#pragma unroll
        for (int k = 0; k < EDGE_REPR; k++) {
            unsigned long long ek = pk2(er[k], er[k]);
            const ulonglong2* w = (const ulonglong2*)(sm + SM_W1 + k * HID);
#pragma unroll
            for (int j = 0; j < HID / 4; j++) {
                ulonglong2 t = w[j];
                fma2(a1[2 * j], ek, t.x);
                fma2(a1[2 * j + 1], ek, t.y);
            }
        }
    }
    float r1[HID];
#pragma unroll
    for (int j = 0; j < HID / 2; j++) upk2(a1[j], r1[2 * j], r1[2 * j + 1]);
#pragma unroll
    for (int j = 0; j < HID; j++) r1[j] = fmaxf(r1[j], 0.f);

    // -------- enc2: 64 -> 32, relu --------
    unsigned long long a2[EMB / 2];
    {
        const unsigned long long* bp = (const unsigned long long*)(sm + SM_B2);
#pragma unroll
        for (int j = 0; j < EMB / 2; j++) a2[j] = bp[j];
#pragma unroll
        for (int k = 0; k < HID; k++) {
            unsigned long long rk = pk2(r1[k], r1[k]);
            const ulonglong2* w = (const ulonglong2*)(sm + SM_W2 + k * EMB);
#pragma unroll
            for (int j = 0; j < EMB / 4; j++) {
                ulonglong2 t = w[j];
                fma2(a2[2 * j], rk, t.x);
                fma2(a2[2 * j + 1], rk, t.y);
            }
        }
    }
    float lat[EMB];
#pragma unroll
    for (int j = 0; j < EMB / 2; j++) upk2(a2[j], lat[2 * j], lat[2 * j + 1]);
#pragma unroll
    for (int j = 0; j < EMB; j++) lat[j] = fmaxf(lat[j], 0.f);

    // -------- dec1: 32 -> 64, relu --------
    unsigned long long a3[HID / 2];
    {
        const unsigned long long* bp = (const unsigned long long*)(sm + SM_B3);
#pragma unroll
        for (int j = 0; j < HID / 2; j++) a3[j] = bp[j];
#pragma unroll
        for (int k = 0; k < EMB; k++) {
            unsigned long long lk = pk2(lat[k], lat[k]);
            const ulonglong2* w = (const ulonglong2*)(sm + SM_D1 + k * HID);
#pragma unroll
            for (int j = 0; j < HID / 4; j++) {
                ulonglong2 t = w[j];
                fma2(a3[2 * j], lk, t.x);
                fma2(a3[2 * j + 1], lk, t.y);
            }
        }
    }
    float h2[HID];
#pragma unroll
    for (int j = 0; j < HID / 2; j++) upk2(a3[j], h2[2 * j], h2[2 * j + 1]);
#pragma unroll
    for (int j = 0; j < HID; j++) h2[j] = fmaxf(h2[j], 0.f);

    // -------- dec2: 64 -> 74 (padded 76), no relu --------
    unsigned long long a4[D2PAD / 2];
    {
        const unsigned long long* bp = (const unsigned long long*)(sm + SM_B4);
#pragma unroll
        for (int j = 0; j < D2PAD / 2; j++) a4[j] = bp[j];
#pragma unroll
        for (int k = 0; k < HID; k++) {
            unsigned long long hk = pk2(h2[k], h2[k]);
            const ulonglong2* w = (const ulonglong2*)(sm + SM_D2 + k * D2PAD);
#pragma unroll
            for (int j = 0; j < D2PAD / 4; j++) {
                ulonglong2 t = w[j];
                fma2(a4[2 * j], hk, t.x);
                fma2(a4[2 * j + 1], hk, t.y);
            }
        }
    }
    {
        unsigned long long* o = (unsigned long long*)(out_recon + (long long)e * EDGE_REPR);
#pragma unroll
        for (int j = 0; j < EDGE_REPR / 2; j++) o[j] = a4[j];  // pairs 0..36 = cols 0..73
    }
}

// ---------------- launcher ----------------------------------------------------
extern "C" void kernel_launch(void* const* d_in, const int* in_sizes, int n_in,
                              void* d_out, int out_size) {
    const float* nf   = (const float*)d_in[0];
    const void*  ei   = d_in[1];
    const float* ea   = (const float*)d_in[2];
    const void*  srcn = d_in[3];
    const void*  dstn = d_in[4];
    const float* Ws1 = (const float*)d_in[5];
    const float* Wn1 = (const float*)d_in[6];
    const float* b1  = (const float*)d_in[7];
    const float* g1  = (const float*)d_in[8];
    const float* be1 = (const float*)d_in[9];
    const float* Ws2 = (const float*)d_in[10];
    const float* Wn2 = (const float*)d_in[11];
    const float* b2  = (const float*)d_in[12];
    const float* g2  = (const float*)d_in[13];
    const float* be2 = (const float*)d_in[14];
    const float* eW1 = (const float*)d_in[15];
    const float* eb1 = (const float*)d_in[16];
    const float* eW2 = (const float*)d_in[17];
    const float* eb2 = (const float*)d_in[18];
    const float* dW1 = (const float*)d_in[19];
    const float* db1 = (const float*)d_in[20];
    const float* dW2 = (const float*)d_in[21];
    const float* db2 = (const float*)d_in[22];

    float* out_recon = (float*)d_out;                                   // [1M, 74]
    float* out_er    = (float*)d_out + (long long)E_SC * EDGE_REPR;     // [1M, 74]

    const int smem_mlp = SM_TOTAL * sizeof(float);  // 55728 B
    cudaFuncSetAttribute(edge_mlp_kernel, cudaFuncAttributeMaxDynamicSharedMemorySize, smem_mlp);

    // 6 launches; edge_mlp is launch #6 for ncu -s 5 -c 1
    hist_kernel<<<(E_MSG + 255) / 256, 256>>>(ei);
    scan_kernel<<<1, 1024>>>();
    fill_kernel<<<(E_MSG + 255) / 256, 256>>>(ei);
    sage1_kernel<<<N_NODES / 8, 256>>>(nf, Ws1, Wn1, b1, g1, be1, Wn2);
    sage2_kernel<<<N_NODES / 8, 256>>>(Ws2, b2, g2, be2);
    edge_mlp_kernel<<<(E_SC + MLP_THREADS - 1) / MLP_THREADS, MLP_THREADS, smem_mlp>>>(
        srcn, dstn, ea, eW1, eb1, eW2, eb2, dW1, db1, dW2, db2, out_recon, out_er);
}